// round 3
// baseline (speedup 1.0000x reference)
#include <cuda_runtime.h>
#include <cstdint>

#define NUM_CLASSES 100000
#define FEAT_DIM    128
#define BATCH       16384
#define LOSS_WEIGHT 0.01f

// Scratch (static device globals — no allocation).
__device__ float g_counts[NUM_CLASSES];
__device__ int   g_y_is64;   // 1 if labels are int64, 0 if int32

__device__ __forceinline__ int get_label(const void* __restrict__ y, int i) {
    if (g_y_is64) return (int)((const long long*)y)[i];
    return ((const int*)y)[i];
}

// ---------------------------------------------------------------------------
// K1: zero counts + loss; block 0 probes the label dtype.
// int64 labels (< 2^31, non-negative) -> every odd 32-bit word is 0.
// int32 labels -> odd words are other random labels -> almost surely nonzero.
// ---------------------------------------------------------------------------
__global__ void k_zero(const int* __restrict__ y_words,
                       float* __restrict__ loss_out) {
    int i = blockIdx.x * blockDim.x + threadIdx.x;
    if (i < NUM_CLASSES) g_counts[i] = 0.0f;
    if (i == 0) *loss_out = 0.0f;

    if (blockIdx.x == 0) {
        int t = threadIdx.x;                       // 0..255
        unsigned nz = (y_words[2 * t + 1] != 0) ? 1u : 0u;
        nz = __ballot_sync(0xFFFFFFFFu, nz != 0);
        __shared__ unsigned s_nz[8];
        if ((t & 31) == 0) s_nz[t >> 5] = nz;
        __syncthreads();
        if (t == 0) {
            unsigned any = 0;
            #pragma unroll
            for (int w = 0; w < 8; w++) any |= s_nz[w];
            g_y_is64 = (any == 0) ? 1 : 0;
        }
    }
}

// ---------------------------------------------------------------------------
// K2: histogram of labels
// ---------------------------------------------------------------------------
__global__ void k_count(const void* __restrict__ y) {
    int i = blockIdx.x * blockDim.x + threadIdx.x;
    if (i < BATCH) {
        atomicAdd(&g_counts[get_label(y, i)], 1.0f);
    }
}

// ---------------------------------------------------------------------------
// K3: grad[c,d] = ratio_c * centers[c,d]; exact zero for empty classes
// (no centers read there). Scalar f32 (grad base is only 4B-aligned).
// One thread per element, fully coalesced.
// ---------------------------------------------------------------------------
__global__ void k_grad_init(const float* __restrict__ centers,
                            float* __restrict__ grad) {
    int i = blockIdx.x * blockDim.x + threadIdx.x;
    if (i >= NUM_CLASSES * FEAT_DIM) return;
    int c = i >> 7;                 // FEAT_DIM = 128
    float cnt = g_counts[c];
    float out = 0.0f;
    if (cnt > 0.0f) {
        out = (cnt / (1.0f + cnt)) * centers[i];
    }
    grad[i] = out;
}

// ---------------------------------------------------------------------------
// K4: per-sample scatter + fused loss. One warp per sample; each lane
// owns 4 strided floats (lane, lane+32, lane+64, lane+96) -> each of the 4
// scalar REDs is a fully-coalesced 128B warp transaction.
//   grad[y_i, d] -= feat[i, d] / (1 + counts[y_i])   (red.global.add.f32)
//   loss += 0.5*w * sum_d (feat[i,d] - centers[y_i,d])^2
// ---------------------------------------------------------------------------
__global__ void k_scatter_loss(const void* __restrict__ y,
                               const float* __restrict__ feat,
                               const float* __restrict__ centers,
                               float* __restrict__ grad,
                               float* __restrict__ loss_out) {
    int i = blockIdx.x;          // sample
    int lane = threadIdx.x;      // 0..31
    int c = get_label(y, i);

    float inv = 1.0f / (1.0f + g_counts[c]);

    const float* frow = feat + i * FEAT_DIM;
    const float* crow = centers + c * FEAT_DIM;
    float* grow = grad + c * FEAT_DIM;

    float v = 0.0f;
    #pragma unroll
    for (int k = 0; k < 4; k++) {
        int d = lane + 32 * k;
        float f   = frow[d];
        float cen = crow[d];
        float diff = f - cen;
        v += diff * diff;
        float a = -f * inv;
        asm volatile("red.global.add.f32 [%0], %1;"
                     :: "l"(grow + d), "f"(a) : "memory");
    }

    // warp-reduce diff^2, one atomic per sample
    #pragma unroll
    for (int o = 16; o > 0; o >>= 1)
        v += __shfl_down_sync(0xFFFFFFFFu, v, o);
    if (lane == 0)
        atomicAdd(loss_out, LOSS_WEIGHT * 0.5f * v);
}

// ---------------------------------------------------------------------------
extern "C" void kernel_launch(void* const* d_in, const int* in_sizes, int n_in,
                              void* d_out, int out_size) {
    const void*  y       = d_in[0];
    const float* feat    = (const float*)d_in[1];
    const float* centers = (const float*)d_in[2];

    float* out      = (float*)d_out;
    float* loss_out = out;          // output 0: scalar loss
    float* grad     = out + 1;      // output 1: [C, D] grad (4B-aligned only!)

    // K1: zero counts + loss, detect label dtype
    {
        int threads = 256;
        int blocks  = (NUM_CLASSES + threads - 1) / threads;
        k_zero<<<blocks, threads>>>((const int*)y, loss_out);
    }
    // K2: histogram
    {
        int threads = 256;
        int blocks  = (BATCH + threads - 1) / threads;
        k_count<<<blocks, threads>>>(y);
    }
    // K3: grad = ratio * centers
    {
        int total   = NUM_CLASSES * FEAT_DIM;
        int threads = 256;
        int blocks  = (total + threads - 1) / threads;
        k_grad_init<<<blocks, threads>>>(centers, grad);
    }
    // K4: scatter feat term + fused loss (1 warp / sample)
    {
        k_scatter_loss<<<BATCH, 32>>>(y, feat, centers, grad, loss_out);
    }
}

// round 4
// speedup vs baseline: 1.5402x; 1.5402x over previous
#include <cuda_runtime.h>
#include <cstdint>

#define NUM_CLASSES 100000
#define FEAT_DIM    128
#define BATCH       16384
#define LOSS_WEIGHT 0.01f

#define K4_WARPS 8                       // samples per block
#define K4_THREADS (K4_WARPS * 32)

// Scratch (static device globals — no allocation).
__device__ float g_counts[NUM_CLASSES];
__device__ int   g_y_is64;   // 1 if labels are int64, 0 if int32

__device__ __forceinline__ int get_label(const void* __restrict__ y, int i) {
    if (g_y_is64) return (int)((const long long*)y)[i];
    return ((const int*)y)[i];
}

// ---------------------------------------------------------------------------
// K1: zero counts + loss; block 0 probes the label dtype.
// int64 labels (< 2^31, non-negative) -> every odd 32-bit word is 0.
// int32 labels -> odd words are other random labels -> almost surely nonzero.
// ---------------------------------------------------------------------------
__global__ void k_zero(const int* __restrict__ y_words,
                       float* __restrict__ loss_out) {
    int i = blockIdx.x * blockDim.x + threadIdx.x;
    if (i < NUM_CLASSES) g_counts[i] = 0.0f;
    if (i == 0) *loss_out = 0.0f;

    if (blockIdx.x == 0) {
        int t = threadIdx.x;                       // 0..255
        unsigned nz = (y_words[2 * t + 1] != 0) ? 1u : 0u;
        nz = __ballot_sync(0xFFFFFFFFu, nz != 0);
        __shared__ unsigned s_nz[8];
        if ((t & 31) == 0) s_nz[t >> 5] = nz;
        __syncthreads();
        if (t == 0) {
            unsigned any = 0;
            #pragma unroll
            for (int w = 0; w < 8; w++) any |= s_nz[w];
            g_y_is64 = (any == 0) ? 1 : 0;
        }
    }
}

// ---------------------------------------------------------------------------
// K2: histogram of labels
// ---------------------------------------------------------------------------
__global__ void k_count(const void* __restrict__ y) {
    int i = blockIdx.x * blockDim.x + threadIdx.x;
    if (i < BATCH) {
        atomicAdd(&g_counts[get_label(y, i)], 1.0f);
    }
}

// ---------------------------------------------------------------------------
// K3: grad[c,d] = ratio_c * centers[c,d]; exact zero for empty classes
// (no centers read there). Scalar f32 (grad base is only 4B-aligned).
// ---------------------------------------------------------------------------
__global__ void k_grad_init(const float* __restrict__ centers,
                            float* __restrict__ grad) {
    int i = blockIdx.x * blockDim.x + threadIdx.x;
    if (i >= NUM_CLASSES * FEAT_DIM) return;
    int c = i >> 7;                 // FEAT_DIM = 128
    float cnt = g_counts[c];
    float out = 0.0f;
    if (cnt > 0.0f) {
        out = (cnt / (1.0f + cnt)) * centers[i];
    }
    grad[i] = out;
}

// ---------------------------------------------------------------------------
// K4: per-sample scatter + fused loss. 8 warps/block, one sample per warp;
// each lane owns 4 strided floats (lane, +32, +64, +96) -> coalesced.
//   grad[y_i, d] -= feat[i, d] / (1 + counts[y_i])   (red.global.add.f32)
//   loss += 0.5*w * sum_d (feat[i,d] - centers[y_i,d])^2  (1 RED per block)
// ---------------------------------------------------------------------------
__global__ void __launch_bounds__(K4_THREADS)
k_scatter_loss(const void* __restrict__ y,
               const float* __restrict__ feat,
               const float* __restrict__ centers,
               float* __restrict__ grad,
               float* __restrict__ loss_out) {
    int wid  = threadIdx.x >> 5;                 // warp in block
    int lane = threadIdx.x & 31;
    int i = blockIdx.x * K4_WARPS + wid;         // sample
    int c = get_label(y, i);

    float inv = 1.0f / (1.0f + g_counts[c]);

    const float* frow = feat + i * FEAT_DIM;
    const float* crow = centers + c * FEAT_DIM;
    float* grow = grad + c * FEAT_DIM;

    // Batch the loads up front for MLP.
    float f0 = frow[lane],      f1 = frow[lane + 32],
          f2 = frow[lane + 64], f3 = frow[lane + 96];
    float c0 = crow[lane],      c1 = crow[lane + 32],
          c2 = crow[lane + 64], c3 = crow[lane + 96];

    asm volatile("red.global.add.f32 [%0], %1;" :: "l"(grow + lane),      "f"(-f0 * inv) : "memory");
    asm volatile("red.global.add.f32 [%0], %1;" :: "l"(grow + lane + 32), "f"(-f1 * inv) : "memory");
    asm volatile("red.global.add.f32 [%0], %1;" :: "l"(grow + lane + 64), "f"(-f2 * inv) : "memory");
    asm volatile("red.global.add.f32 [%0], %1;" :: "l"(grow + lane + 96), "f"(-f3 * inv) : "memory");

    float d0 = f0 - c0, d1 = f1 - c1, d2 = f2 - c2, d3 = f3 - c3;
    float v = d0 * d0 + d1 * d1 + d2 * d2 + d3 * d3;

    // warp reduce
    #pragma unroll
    for (int o = 16; o > 0; o >>= 1)
        v += __shfl_down_sync(0xFFFFFFFFu, v, o);

    // block reduce: 8 warp partials -> 1 RED per block
    __shared__ float s_part[K4_WARPS];
    if (lane == 0) s_part[wid] = v;
    __syncthreads();
    if (threadIdx.x == 0) {
        float t = 0.0f;
        #pragma unroll
        for (int w = 0; w < K4_WARPS; w++) t += s_part[w];
        t *= LOSS_WEIGHT * 0.5f;
        asm volatile("red.global.add.f32 [%0], %1;" :: "l"(loss_out), "f"(t) : "memory");
    }
}

// ---------------------------------------------------------------------------
extern "C" void kernel_launch(void* const* d_in, const int* in_sizes, int n_in,
                              void* d_out, int out_size) {
    const void*  y       = d_in[0];
    const float* feat    = (const float*)d_in[1];
    const float* centers = (const float*)d_in[2];

    float* out      = (float*)d_out;
    float* loss_out = out;          // output 0: scalar loss
    float* grad     = out + 1;      // output 1: [C, D] grad (4B-aligned only!)

    // K1: zero counts + loss, detect label dtype
    {
        int threads = 256;
        int blocks  = (NUM_CLASSES + threads - 1) / threads;
        k_zero<<<blocks, threads>>>((const int*)y, loss_out);
    }
    // K2: histogram
    {
        int threads = 256;
        int blocks  = (BATCH + threads - 1) / threads;
        k_count<<<blocks, threads>>>(y);
    }
    // K3: grad = ratio * centers
    {
        int total   = NUM_CLASSES * FEAT_DIM;
        int threads = 256;
        int blocks  = (total + threads - 1) / threads;
        k_grad_init<<<blocks, threads>>>(centers, grad);
    }
    // K4: scatter feat term + fused loss (8 samples / block)
    {
        k_scatter_loss<<<BATCH / K4_WARPS, K4_THREADS>>>(y, feat, centers,
                                                         grad, loss_out);
    }
}

// round 5
// speedup vs baseline: 2.6384x; 1.7130x over previous
#include <cuda_runtime.h>
#include <cstdint>

#define NUM_CLASSES 100000
#define FEAT_DIM    128
#define BATCH       16384
#define LOSS_WEIGHT 0.01f
#define TOTAL       (NUM_CLASSES * FEAT_DIM)      // 12,800,000

#define K4_WARPS   8                              // warps per block
#define K4_SPW     2                              // samples per warp
#define K4_THREADS (K4_WARPS * 32)

// Number of shifted float4 vectors in K3: elements [3 .. 3+4*NV) aligned 16B.
#define K3_NV ((TOTAL - 3) / 4)                   // 3,199,999 (tail: 1 elem)

// Scratch (static device globals — no allocation).
__device__ float g_counts[NUM_CLASSES];
__device__ int   g_y_is64;   // 1 if labels are int64, 0 if int32

__device__ __forceinline__ int get_label(const void* __restrict__ y, int i) {
    if (g_y_is64) return (int)((const long long*)y)[i];
    return ((const int*)y)[i];
}

// ---------------------------------------------------------------------------
// K1: zero counts + loss; block 0 probes the label dtype.
// ---------------------------------------------------------------------------
__global__ void k_zero(const int* __restrict__ y_words,
                       float* __restrict__ loss_out) {
    int i = blockIdx.x * blockDim.x + threadIdx.x;
    if (i < NUM_CLASSES) g_counts[i] = 0.0f;
    if (i == 0) *loss_out = 0.0f;

    if (blockIdx.x == 0) {
        int t = threadIdx.x;                       // 0..255
        unsigned nz = (y_words[2 * t + 1] != 0) ? 1u : 0u;
        nz = __ballot_sync(0xFFFFFFFFu, nz != 0);
        __shared__ unsigned s_nz[8];
        if ((t & 31) == 0) s_nz[t >> 5] = nz;
        __syncthreads();
        if (t == 0) {
            unsigned any = 0;
            #pragma unroll
            for (int w = 0; w < 8; w++) any |= s_nz[w];
            g_y_is64 = (any == 0) ? 1 : 0;
        }
    }
}

// ---------------------------------------------------------------------------
// K2: histogram of labels
// ---------------------------------------------------------------------------
__global__ void k_count(const void* __restrict__ y) {
    int i = blockIdx.x * blockDim.x + threadIdx.x;
    if (i < BATCH) {
        atomicAdd(&g_counts[get_label(y, i)], 1.0f);
    }
}

// ---------------------------------------------------------------------------
// K3: grad[c,d] = ratio_c * centers[c,d] with SHIFTED float4 stores.
// grad = out+1 (4B aligned); elements i≡3 (mod 4) are at 16B boundaries, so
// thread j stores elements [4j+3, 4j+7) as one aligned float4.
// A vector can cross a class boundary only between its 1st and 2nd element
// (boundary at multiple of 128; e0 = 4j+3, e1 = 4(j+1)): e0 in cA, e1..e3 in cB.
// Fully-empty vectors (ratio 0) skip the centers loads.
// Thread j == K3_NV handles the 3-element head and the 1-element tail.
// ---------------------------------------------------------------------------
__global__ void k_grad_init(const float* __restrict__ centers,
                            float* __restrict__ grad) {
    int j = blockIdx.x * blockDim.x + threadIdx.x;
    if (j < K3_NV) {
        int e0 = 4 * j + 3;
        int cA = e0 >> 7;
        int cB = (e0 + 3) >> 7;
        float cntA = g_counts[cA];
        float rA = (cntA > 0.0f) ? (cntA / (1.0f + cntA)) : 0.0f;
        float rB = rA;
        if (cB != cA) {
            float cntB = g_counts[cB];
            rB = (cntB > 0.0f) ? (cntB / (1.0f + cntB)) : 0.0f;
        }
        float4 o = make_float4(0.f, 0.f, 0.f, 0.f);
        if (rA != 0.0f || rB != 0.0f) {
            o.x = rA * __ldg(centers + e0);
            o.y = rB * __ldg(centers + e0 + 1);
            o.z = rB * __ldg(centers + e0 + 2);
            o.w = rB * __ldg(centers + e0 + 3);
        }
        *reinterpret_cast<float4*>(grad + e0) = o;
    } else if (j == K3_NV) {
        // head: elements 0,1,2 (class 0)
        float cnt0 = g_counts[0];
        float r0 = (cnt0 > 0.0f) ? (cnt0 / (1.0f + cnt0)) : 0.0f;
        grad[0] = r0 * centers[0];
        grad[1] = r0 * centers[1];
        grad[2] = r0 * centers[2];
        // tail: element TOTAL-1 (class NUM_CLASSES-1)
        float cntL = g_counts[NUM_CLASSES - 1];
        float rL = (cntL > 0.0f) ? (cntL / (1.0f + cntL)) : 0.0f;
        grad[TOTAL - 1] = rL * centers[TOTAL - 1];
    }
}

// ---------------------------------------------------------------------------
// K4: scatter + fused loss. 8 warps/block, 2 samples per warp (front-batched
// loads for MLP=16+). Each lane owns 4 strided floats per sample.
// ---------------------------------------------------------------------------
__global__ void __launch_bounds__(K4_THREADS)
k_scatter_loss(const void* __restrict__ y,
               const float* __restrict__ feat,
               const float* __restrict__ centers,
               float* __restrict__ grad,
               float* __restrict__ loss_out) {
    int wid  = threadIdx.x >> 5;
    int lane = threadIdx.x & 31;
    int i0 = (blockIdx.x * K4_WARPS + wid) * K4_SPW;   // first sample
    int i1 = i0 + 1;

    int cA = get_label(y, i0);
    int cB = get_label(y, i1);
    float invA = 1.0f / (1.0f + g_counts[cA]);
    float invB = 1.0f / (1.0f + g_counts[cB]);

    const float* fA = feat + i0 * FEAT_DIM;
    const float* fB = feat + i1 * FEAT_DIM;
    const float* eA = centers + cA * FEAT_DIM;
    const float* eB = centers + cB * FEAT_DIM;
    float* gA = grad + cA * FEAT_DIM;
    float* gB = grad + cB * FEAT_DIM;

    // Front-batch all 16 loads for maximum MLP.
    float a0 = fA[lane],      a1 = fA[lane + 32],
          a2 = fA[lane + 64], a3 = fA[lane + 96];
    float b0 = fB[lane],      b1 = fB[lane + 32],
          b2 = fB[lane + 64], b3 = fB[lane + 96];
    float p0 = eA[lane],      p1 = eA[lane + 32],
          p2 = eA[lane + 64], p3 = eA[lane + 96];
    float q0 = eB[lane],      q1 = eB[lane + 32],
          q2 = eB[lane + 64], q3 = eB[lane + 96];

    asm volatile("red.global.add.f32 [%0], %1;" :: "l"(gA + lane),      "f"(-a0 * invA) : "memory");
    asm volatile("red.global.add.f32 [%0], %1;" :: "l"(gA + lane + 32), "f"(-a1 * invA) : "memory");
    asm volatile("red.global.add.f32 [%0], %1;" :: "l"(gA + lane + 64), "f"(-a2 * invA) : "memory");
    asm volatile("red.global.add.f32 [%0], %1;" :: "l"(gA + lane + 96), "f"(-a3 * invA) : "memory");
    asm volatile("red.global.add.f32 [%0], %1;" :: "l"(gB + lane),      "f"(-b0 * invB) : "memory");
    asm volatile("red.global.add.f32 [%0], %1;" :: "l"(gB + lane + 32), "f"(-b1 * invB) : "memory");
    asm volatile("red.global.add.f32 [%0], %1;" :: "l"(gB + lane + 64), "f"(-b2 * invB) : "memory");
    asm volatile("red.global.add.f32 [%0], %1;" :: "l"(gB + lane + 96), "f"(-b3 * invB) : "memory");

    float d;
    float v = 0.0f;
    d = a0 - p0; v += d * d;   d = a1 - p1; v += d * d;
    d = a2 - p2; v += d * d;   d = a3 - p3; v += d * d;
    d = b0 - q0; v += d * d;   d = b1 - q1; v += d * d;
    d = b2 - q2; v += d * d;   d = b3 - q3; v += d * d;

    #pragma unroll
    for (int o = 16; o > 0; o >>= 1)
        v += __shfl_down_sync(0xFFFFFFFFu, v, o);

    __shared__ float s_part[K4_WARPS];
    if (lane == 0) s_part[wid] = v;
    __syncthreads();
    if (threadIdx.x == 0) {
        float t = 0.0f;
        #pragma unroll
        for (int w = 0; w < K4_WARPS; w++) t += s_part[w];
        t *= LOSS_WEIGHT * 0.5f;
        asm volatile("red.global.add.f32 [%0], %1;" :: "l"(loss_out), "f"(t) : "memory");
    }
}

// ---------------------------------------------------------------------------
extern "C" void kernel_launch(void* const* d_in, const int* in_sizes, int n_in,
                              void* d_out, int out_size) {
    const void*  y       = d_in[0];
    const float* feat    = (const float*)d_in[1];
    const float* centers = (const float*)d_in[2];

    float* out      = (float*)d_out;
    float* loss_out = out;          // output 0: scalar loss
    float* grad     = out + 1;      // output 1: [C, D] grad (4B-aligned only!)

    // K1: zero counts + loss, detect label dtype
    {
        int threads = 256;
        int blocks  = (NUM_CLASSES + threads - 1) / threads;
        k_zero<<<blocks, threads>>>((const int*)y, loss_out);
    }
    // K2: histogram
    {
        int threads = 256;
        int blocks  = (BATCH + threads - 1) / threads;
        k_count<<<blocks, threads>>>(y);
    }
    // K3: grad = ratio * centers (shifted float4 stores)
    {
        int threads = 256;
        int blocks  = (K3_NV + 1 + threads - 1) / threads;
        k_grad_init<<<blocks, threads>>>(centers, grad);
    }
    // K4: scatter feat term + fused loss (16 samples / block)
    {
        k_scatter_loss<<<BATCH / (K4_WARPS * K4_SPW), K4_THREADS>>>(
            y, feat, centers, grad, loss_out);
    }
}

// round 6
// speedup vs baseline: 2.8472x; 1.0792x over previous
#include <cuda_runtime.h>
#include <cstdint>

#define NUM_CLASSES 100000
#define FEAT_DIM    128
#define BATCH       16384
#define LOSS_WEIGHT 0.01f
#define TOTAL       (NUM_CLASSES * FEAT_DIM)      // 12,800,000

#define K4_WARPS   8                              // warps per block
#define K4_SPW     4                              // samples per warp
#define K4_THREADS (K4_WARPS * 32)

// Number of shifted float4 vectors in K3: elements [3 .. 3+4*NV) aligned 16B.
#define K3_NV ((TOTAL - 3) / 4)                   // 3,199,999 (tail: 1 elem)

// Scratch (static device globals — no allocation).
__device__ float g_counts[NUM_CLASSES];           // 16B-aligned
__device__ int   g_y_is64;   // 1 if labels are int64, 0 if int32

__device__ __forceinline__ int get_label(const void* __restrict__ y, int i) {
    if (g_y_is64) return (int)((const long long*)y)[i];
    return ((const int*)y)[i];
}

// ---------------------------------------------------------------------------
// K1: zero counts (float4) + loss; block 0 probes the label dtype.
// int64 labels (< 2^31) -> every odd 32-bit word is 0; int32 -> almost
// surely some odd word nonzero in the first 256 pairs.
// ---------------------------------------------------------------------------
__global__ void k_zero(const int* __restrict__ y_words,
                       float* __restrict__ loss_out) {
    int i = blockIdx.x * blockDim.x + threadIdx.x;
    if (i < NUM_CLASSES / 4) {
        reinterpret_cast<float4*>(g_counts)[i] =
            make_float4(0.f, 0.f, 0.f, 0.f);
    }
    if (i == 0) *loss_out = 0.0f;

    if (blockIdx.x == 0) {
        int t = threadIdx.x;                       // 0..255
        unsigned nz = (y_words[2 * t + 1] != 0) ? 1u : 0u;
        nz = __ballot_sync(0xFFFFFFFFu, nz != 0);
        __shared__ unsigned s_nz[8];
        if ((t & 31) == 0) s_nz[t >> 5] = nz;
        __syncthreads();
        if (t == 0) {
            unsigned any = 0;
            #pragma unroll
            for (int w = 0; w < 8; w++) any |= s_nz[w];
            g_y_is64 = (any == 0) ? 1 : 0;
        }
    }
}

// ---------------------------------------------------------------------------
// K2: histogram of labels
// ---------------------------------------------------------------------------
__global__ void k_count(const void* __restrict__ y) {
    int i = blockIdx.x * blockDim.x + threadIdx.x;
    if (i < BATCH) {
        atomicAdd(&g_counts[get_label(y, i)], 1.0f);
    }
}

// ---------------------------------------------------------------------------
// K3: grad[c,d] = ratio_c * centers[c,d] with SHIFTED float4 stores
// (grad = out+1 is 4B-aligned; elements i≡3 mod 4 sit on 16B boundaries).
// Streaming stores (__stcs) keep the 51MB grad write from evicting the hot
// centers rows in L2 that K4 gathers next. Empty-class vectors skip the
// centers loads entirely (~85% of rows).
// ---------------------------------------------------------------------------
__global__ void k_grad_init(const float* __restrict__ centers,
                            float* __restrict__ grad) {
    int j = blockIdx.x * blockDim.x + threadIdx.x;
    if (j < K3_NV) {
        int e0 = 4 * j + 3;
        int cA = e0 >> 7;
        int cB = (e0 + 3) >> 7;
        float cntA = g_counts[cA];
        float rA = (cntA > 0.0f) ? (cntA / (1.0f + cntA)) : 0.0f;
        float rB = rA;
        if (cB != cA) {
            float cntB = g_counts[cB];
            rB = (cntB > 0.0f) ? (cntB / (1.0f + cntB)) : 0.0f;
        }
        float4 o = make_float4(0.f, 0.f, 0.f, 0.f);
        if (rA != 0.0f || rB != 0.0f) {
            o.x = rA * __ldg(centers + e0);
            o.y = rB * __ldg(centers + e0 + 1);
            o.z = rB * __ldg(centers + e0 + 2);
            o.w = rB * __ldg(centers + e0 + 3);
        }
        __stcs(reinterpret_cast<float4*>(grad + e0), o);
    } else if (j == K3_NV) {
        // head: elements 0,1,2 (class 0)
        float cnt0 = g_counts[0];
        float r0 = (cnt0 > 0.0f) ? (cnt0 / (1.0f + cnt0)) : 0.0f;
        grad[0] = r0 * centers[0];
        grad[1] = r0 * centers[1];
        grad[2] = r0 * centers[2];
        // tail: element TOTAL-1 (last class)
        float cntL = g_counts[NUM_CLASSES - 1];
        float rL = (cntL > 0.0f) ? (cntL / (1.0f + cntL)) : 0.0f;
        grad[TOTAL - 1] = rL * centers[TOTAL - 1];
    }
}

// ---------------------------------------------------------------------------
// K4: scatter + fused loss. 8 warps/block, 4 samples per warp.
// All 32 loads per warp front-batched (scalar, lane+32k pattern -> every
// load AND every RED is a fully-coalesced 128B warp transaction).
// ---------------------------------------------------------------------------
__global__ void __launch_bounds__(K4_THREADS)
k_scatter_loss(const void* __restrict__ y,
               const float* __restrict__ feat,
               const float* __restrict__ centers,
               float* __restrict__ grad,
               float* __restrict__ loss_out) {
    int wid  = threadIdx.x >> 5;
    int lane = threadIdx.x & 31;
    int base = (blockIdx.x * K4_WARPS + wid) * K4_SPW;

    int   c[K4_SPW];
    float inv[K4_SPW];
    const float* frow[K4_SPW];
    const float* crow[K4_SPW];

    #pragma unroll
    for (int s = 0; s < K4_SPW; s++)
        c[s] = get_label(y, base + s);
    #pragma unroll
    for (int s = 0; s < K4_SPW; s++) {
        inv[s]  = 1.0f / (1.0f + g_counts[c[s]]);
        frow[s] = feat + (base + s) * FEAT_DIM;
        crow[s] = centers + c[s] * FEAT_DIM;
    }

    // Front-batch all 32 loads for maximum MLP.
    float f[K4_SPW][4], e[K4_SPW][4];
    #pragma unroll
    for (int s = 0; s < K4_SPW; s++)
        #pragma unroll
        for (int k = 0; k < 4; k++)
            f[s][k] = frow[s][lane + 32 * k];
    #pragma unroll
    for (int s = 0; s < K4_SPW; s++)
        #pragma unroll
        for (int k = 0; k < 4; k++)
            e[s][k] = crow[s][lane + 32 * k];

    #pragma unroll
    for (int s = 0; s < K4_SPW; s++) {
        float* grow = grad + c[s] * FEAT_DIM;
        #pragma unroll
        for (int k = 0; k < 4; k++) {
            asm volatile("red.global.add.f32 [%0], %1;"
                         :: "l"(grow + lane + 32 * k),
                            "f"(-f[s][k] * inv[s]) : "memory");
        }
    }

    float v = 0.0f;
    #pragma unroll
    for (int s = 0; s < K4_SPW; s++)
        #pragma unroll
        for (int k = 0; k < 4; k++) {
            float d = f[s][k] - e[s][k];
            v += d * d;
        }

    #pragma unroll
    for (int o = 16; o > 0; o >>= 1)
        v += __shfl_down_sync(0xFFFFFFFFu, v, o);

    __shared__ float s_part[K4_WARPS];
    if (lane == 0) s_part[wid] = v;
    __syncthreads();
    if (threadIdx.x == 0) {
        float t = 0.0f;
        #pragma unroll
        for (int w = 0; w < K4_WARPS; w++) t += s_part[w];
        t *= LOSS_WEIGHT * 0.5f;
        asm volatile("red.global.add.f32 [%0], %1;"
                     :: "l"(loss_out), "f"(t) : "memory");
    }
}

// ---------------------------------------------------------------------------
extern "C" void kernel_launch(void* const* d_in, const int* in_sizes, int n_in,
                              void* d_out, int out_size) {
    const void*  y       = d_in[0];
    const float* feat    = (const float*)d_in[1];
    const float* centers = (const float*)d_in[2];

    float* out      = (float*)d_out;
    float* loss_out = out;          // output 0: scalar loss
    float* grad     = out + 1;      // output 1: [C, D] grad (4B-aligned only!)

    // K1: zero counts (vectorized) + loss, detect label dtype
    {
        int threads = 256;
        int blocks  = (NUM_CLASSES / 4 + threads - 1) / threads;  // 98
        k_zero<<<blocks, threads>>>((const int*)y, loss_out);
    }
    // K2: histogram
    {
        int threads = 256;
        int blocks  = (BATCH + threads - 1) / threads;
        k_count<<<blocks, threads>>>(y);
    }
    // K3: grad = ratio * centers (shifted float4 streaming stores)
    {
        int threads = 256;
        int blocks  = (K3_NV + 1 + threads - 1) / threads;
        k_grad_init<<<blocks, threads>>>(centers, grad);
    }
    // K4: scatter feat term + fused loss (32 samples / block)
    {
        k_scatter_loss<<<BATCH / (K4_WARPS * K4_SPW), K4_THREADS>>>(
            y, feat, centers, grad, loss_out);
    }
}